// round 14
// baseline (speedup 1.0000x reference)
#include <cuda_runtime.h>
#include <cuda_fp16.h>
#include <cstdint>

#define Bq 4
#define Tq 12
#define Nq 4096
#define Fq 32

// ---------------------------------------------------------------------------
// PTX helpers — Ampere-era only (compute_103-safe: tcgen05 rejected by ptxas
// at the compute_103 virtual arch; s8 IMMA slow (R5); term-major order slow
// (R6); per-batch multi-stream graphs trip the upload-residue guard (R9);
// batch-pair L2 chaining neutral (R13: GEMMs are latency- not DRAM-bound)).
// ---------------------------------------------------------------------------
__device__ __forceinline__ uint32_t smem_to_u32(const void* p) {
    uint32_t a;
    asm("{ .reg .u64 t; cvta.to.shared.u64 t, %1; cvt.u32.u64 %0, t; }" : "=r"(a) : "l"(p));
    return a;
}

#define CP_ASYNC16(dst, src) \
    asm volatile("cp.async.cg.shared.global [%0], [%1], 16;" :: "r"(dst), "l"(src) : "memory")
#define CP_COMMIT() asm volatile("cp.async.commit_group;" ::: "memory")
#define CP_WAIT0()  asm volatile("cp.async.wait_group 0;" ::: "memory")
#define CP_WAIT1()  asm volatile("cp.async.wait_group 1;" ::: "memory")

__device__ __forceinline__ void ldsm4(uint32_t addr, uint32_t* r) {
    asm volatile("ldmatrix.sync.aligned.m8n8.x4.shared.b16 {%0,%1,%2,%3}, [%4];"
                 : "=r"(r[0]), "=r"(r[1]), "=r"(r[2]), "=r"(r[3]) : "r"(addr));
}
__device__ __forceinline__ void mma_f16(float* d, const uint32_t* a, uint32_t b0, uint32_t b1) {
    asm volatile("mma.sync.aligned.m16n8k16.row.col.f32.f16.f16.f32 "
                 "{%0,%1,%2,%3},{%4,%5,%6,%7},{%8,%9},{%0,%1,%2,%3};"
                 : "+f"(d[0]), "+f"(d[1]), "+f"(d[2]), "+f"(d[3])
                 : "r"(a[0]), "r"(a[1]), "r"(a[2]), "r"(a[3]), "r"(b0), "r"(b1));
}

// ---------------------------------------------------------------------------
// Device scratch
// ---------------------------------------------------------------------------
__device__ __align__(128) __half g_Ah[(size_t)Bq * Nq * Nq];
__device__ __align__(128) __half g_xt[(size_t)Bq * Tq * Fq * Nq];   // [b][t*32+f][n]
__device__ __align__(128) __half g_St[(size_t)Bq * 2 * Fq * Nq];    // [b][64][n]  (h|m)
__device__ __align__(128) __half g_ht[(size_t)Bq * Fq * Nq];        // [b][32][n]  (h_mid)

__device__ __align__(128) float g_YX [(size_t)Bq * Tq * Nq * Fq];
__device__ __align__(128) float g_Y1m[(size_t)Bq * Nq * Fq];        // adj@m (for gates2)
__device__ __align__(128) float g_m  [(size_t)Bq * Nq * Fq];
__device__ __align__(128) float g_c  [(size_t)Bq * Nq * Fq];

__device__ __forceinline__ float sigf(float x) { return 1.0f / (1.0f + __expf(-x)); }

// ---------------------------------------------------------------------------
// adj -> fp16
// ---------------------------------------------------------------------------
__global__ __launch_bounds__(256) void convert_adj(const float* __restrict__ adj) {
    size_t i = (size_t)blockIdx.x * 256 + threadIdx.x;
    float4 v = ((const float4*)adj)[i];
    __half2 p0 = __floats2half2_rn(v.x, v.y);
    __half2 p1 = __floats2half2_rn(v.z, v.w);
    uint2 w;
    w.x = *(uint32_t*)&p0; w.y = *(uint32_t*)&p1;
    ((uint2*)g_Ah)[i] = w;
}

__global__ void init_state() {
    int i = blockIdx.x * blockDim.x + threadIdx.x;
    if (i < Bq * Nq * Fq) { g_m[i] = 1.0f; g_c[i] = 1.0f; }
    if (i < Bq * 2 * Fq * Nq) g_St[i] = __float2half(1.0f);
}

// ---------------------------------------------------------------------------
// transpose x: [z][4096][32] fp32 -> [z][32][4096] fp16
// ---------------------------------------------------------------------------
__global__ __launch_bounds__(256) void trans_x(const float* __restrict__ V,
                                               __half* __restrict__ T) {
    __shared__ float tile[64][33];
    const int z = blockIdx.z;
    const int n0 = blockIdx.x * 64;
    const float* v = V + (size_t)z * Nq * 32 + (size_t)n0 * 32;
    const int tid = threadIdx.x;
#pragma unroll
    for (int idx = tid; idx < 64 * 32; idx += 256)
        tile[idx >> 5][idx & 31] = v[idx];
    __syncthreads();
    __half* t = T + (size_t)z * 32 * Nq;
#pragma unroll
    for (int idx = tid; idx < 64 * 32; idx += 256) {
        int f = idx >> 6, j = idx & 63;
        t[(size_t)f * Nq + n0 + j] = __float2half(tile[j][f]);
    }
}

// ===========================================================================
// Shared GEMM mainloop body (BM=128, superchunk K=64, 3 superbuffers,
// one barrier per superchunk). Produces acc[2][NF][4] per warp.
// Layout: 8 warps = 4(m) x 2(n). A rows m0..m0+127, B rows = output cols.
// ===========================================================================
#define GEMM_MAINLOOP(BN_, NSS_, gA_, gB_)                                     \
    constexpr int RB = 80;                                                     \
    constexpr int A_BYTES = 128 * RB;                                          \
    constexpr int B_BYTES = (BN_) * RB;                                        \
    constexpr int OFF_B = A_BYTES;                                             \
    constexpr int SUB = A_BYTES + B_BYTES;                                     \
    constexpr int STAGE = 2 * SUB;                                             \
    constexpr int WN = (BN_) / 2;                                              \
    constexpr int NF = WN / 8;                                                 \
    constexpr int NB = (NF + 1) / 2;                                           \
    const uint32_t sbase = smem_to_u32(smc);                                   \
    const int tid = threadIdx.x;                                               \
    const int wid = tid >> 5, lane = tid & 31;                                 \
    const int wm = wid & 3, wn = wid >> 2;                                     \
    const int arow = tid >> 2;                                                 \
    const int acol = tid & 3;                                                  \
    const int brow = ((BN_) == 64) ? (tid >> 2) : ((tid & 127) >> 2);          \
    const bool bact = ((BN_) == 64) || (tid < 128);                            \
    float acc[2][NF][4];                                                       \
    _Pragma("unroll")                                                          \
    for (int mf = 0; mf < 2; mf++)                                             \
        _Pragma("unroll")                                                      \
        for (int nf = 0; nf < NF; nf++)                                        \
            _Pragma("unroll")                                                  \
            for (int q = 0; q < 4; q++) acc[mf][nf][q] = 0.0f;                 \
    auto issue = [&](int s) {                                                  \
        const uint32_t st = sbase + (uint32_t)(s % 3) * STAGE;                 \
        _Pragma("unroll")                                                      \
        for (int kc = 0; kc < 2; kc++) {                                       \
            const uint32_t sb = st + kc * SUB;                                 \
            const int k0 = s * 64 + kc * 32;                                   \
            _Pragma("unroll")                                                  \
            for (int rep = 0; rep < 2; rep++) {                                \
                int r = rep * 64 + arow;                                       \
                CP_ASYNC16(sb + r * RB + acol * 16,                            \
                           (gA_) + (size_t)r * Nq + k0 + acol * 8);            \
            }                                                                  \
            if (bact)                                                          \
                CP_ASYNC16(sb + OFF_B + brow * RB + acol * 16,                 \
                           (gB_) + (size_t)brow * Nq + k0 + acol * 8);         \
        }                                                                      \
    };                                                                         \
    issue(0); CP_COMMIT();                                                     \
    issue(1); CP_COMMIT();                                                     \
    const int a_r = (lane & 15);                                               \
    const int a_k = (lane >> 4) * 16;                                          \
    const int b_r = ((lane >> 4) << 3) + (lane & 7);                           \
    const int b_k = ((lane >> 3) & 1) * 16;                                    \
    _Pragma("unroll 1")                                                        \
    for (int s = 0; s < (NSS_); s++) {                                         \
        if (s + 1 < (NSS_)) { CP_WAIT1(); } else { CP_WAIT0(); }               \
        __syncthreads();                                                       \
        if (s + 2 < (NSS_)) { issue(s + 2); CP_COMMIT(); }                     \
        const uint32_t st = sbase + (uint32_t)(s % 3) * STAGE;                 \
        _Pragma("unroll")                                                      \
        for (int kc = 0; kc < 2; kc++) {                                       \
            const uint32_t sb = st + kc * SUB;                                 \
            _Pragma("unroll")                                                  \
            for (int ks = 0; ks < 2; ks++) {                                   \
                uint32_t ah[2][4];                                             \
                _Pragma("unroll")                                              \
                for (int mf = 0; mf < 2; mf++)                                 \
                    ldsm4(sb + (wm * 32 + mf * 16 + a_r) * RB + ks * 32 + a_k, \
                          ah[mf]);                                             \
                uint32_t bh[NB][4];                                            \
                _Pragma("unroll")                                              \
                for (int nb = 0; nb < NB; nb++)                                \
                    ldsm4(sb + OFF_B + (wn * WN + nb * 16 + b_r) * RB          \
                              + ks * 32 + b_k, bh[nb]);                        \
                _Pragma("unroll")                                              \
                for (int mf = 0; mf < 2; mf++)                                 \
                    _Pragma("unroll")                                          \
                    for (int nf = 0; nf < NF; nf++) {                          \
                        const int nb = nf >> 1, pr = (nf & 1) * 2;             \
                        mma_f16(acc[mf][nf], ah[mf], bh[nb][pr], bh[nb][pr+1]);\
                    }                                                          \
            }                                                                  \
        }                                                                      \
    }

// ---------------------------------------------------------------------------
// Precompute GEMM (adj @ x slabs) — pure GEMM with global fp32 output.
// ---------------------------------------------------------------------------
__global__ __launch_bounds__(256, 2) void pre_gemm(const __half* __restrict__ B_g,
                                                   float* __restrict__ Y) {
    extern __shared__ char smc[];
    const int z = blockIdx.z;
    const int m0 = blockIdx.x * 128;
    const __half* gA = g_Ah + (size_t)z * Nq * Nq + (size_t)m0 * Nq;
    const __half* gB = B_g + (size_t)z * (Tq * Fq * Nq);
    GEMM_MAINLOOP(64, 64, gA, gB)

    // Y layout: [b][t][n][32], this slab covers 2 t's (cols 0..31 -> t0, 32..63 -> t1)
    float* yb = Y + (size_t)z * Tq * Nq * Fq;
#pragma unroll
    for (int mf = 0; mf < 2; mf++)
#pragma unroll
        for (int nf = 0; nf < NF; nf++) {
            int r = m0 + wm * 32 + mf * 16 + (lane >> 2);
            int cj = wn * WN + nf * 8 + (lane & 3) * 2;
            size_t off = (size_t)(cj >> 5) * (Nq * Fq) + (cj & 31);
            float* o0 = yb + (size_t)r * Fq + off;
            float* o1 = yb + (size_t)(r + 8) * Fq + off;
            *(float2*)o0 = make_float2(acc[mf][nf][0], acc[mf][nf][1]);
            *(float2*)o1 = make_float2(acc[mf][nf][2], acc[mf][nf][3]);
        }
}

// ---------------------------------------------------------------------------
// step1: Y1 = adj @ [h|m]^T (BN=64, full K) FUSED with gates1.
// h-half of Y1 stays in smem; m-half -> g_Y1m (for step2). Then gate math
// (row-blocked R10 pattern) using packed W in smem; outputs c-update + h_mid.
// ---------------------------------------------------------------------------
__global__ __launch_bounds__(256, 2) void step1_kernel(const float* __restrict__ W,
                                                       const float* __restrict__ bias,
                                                       int t, float* __restrict__ last_c) {
    extern __shared__ char smc[];
    const int z = blockIdx.z;
    const int m0 = blockIdx.x * 128;
    const __half* gA = g_Ah + (size_t)z * Nq * Nq + (size_t)m0 * Nq;
    const __half* gB = g_St + (size_t)z * 64 * Nq;
    GEMM_MAINLOOP(64, 64, gA, gB)

    // ---- epilogue: stash yh in smem, ym to global ----
    float* ys  = (float*)smc;                         // [128][34] fp32 (17408 B)
    float4* Wp = (float4*)(smc + 17408);              // 4096 float4 (65536 B)
    float4* bp = (float4*)(smc + 17408 + 65536);      // 128 float4 (2048 B)
    __syncthreads();   // all warps done reading GEMM smem buffers

    if (wn == 0) {
#pragma unroll
        for (int mf = 0; mf < 2; mf++)
#pragma unroll
            for (int nf = 0; nf < NF; nf++) {
                int lr = wm * 32 + mf * 16 + (lane >> 2);
                int c = nf * 8 + (lane & 3) * 2;
                *(float2*)&ys[lr * 34 + c] = make_float2(acc[mf][nf][0], acc[mf][nf][1]);
                *(float2*)&ys[(lr + 8) * 34 + c] = make_float2(acc[mf][nf][2], acc[mf][nf][3]);
            }
    } else {
        float* ym = g_Y1m + ((size_t)z * Nq + m0) * Fq;
#pragma unroll
        for (int mf = 0; mf < 2; mf++)
#pragma unroll
            for (int nf = 0; nf < NF; nf++) {
                int lr = wm * 32 + mf * 16 + (lane >> 2);
                int c = nf * 8 + (lane & 3) * 2;
                *(float2*)&ym[(size_t)lr * Fq + c] = make_float2(acc[mf][nf][0], acc[mf][nf][1]);
                *(float2*)&ym[(size_t)(lr + 8) * Fq + c] = make_float2(acc[mf][nf][2], acc[mf][nf][3]);
            }
    }
    // load packed W (gates 0..7) + bias
    for (int idx = tid; idx < 4096; idx += 256) {
        int l = idx & 31, p = (idx >> 5) & 3, k = idx >> 7;
        const float* W0 = W + (2 * p) * (Fq * 2 * Fq) + k * (2 * Fq);
        const float* W1 = W + (2 * p + 1) * (Fq * 2 * Fq) + k * (2 * Fq);
        Wp[idx] = make_float4(W0[l], W0[l + 32], W1[l], W1[l + 32]);
    }
    if (tid < 128) {
        int l = tid & 31, p = tid >> 5;
        bp[p * 32 + l] = make_float4(bias[(2 * p) * 64 + l], bias[(2 * p) * 64 + 32 + l],
                                     bias[(2 * p + 1) * 64 + l], bias[(2 * p + 1) * 64 + 32 + l]);
    }
    __syncthreads();

    // ---- gates1: each warp handles 16 CTA-local rows (4 blocks of 4) ----
    const int l = lane;
#pragma unroll 1
    for (int blk = 0; blk < 4; blk++) {
        int lr0 = wid * 16 + blk * 4;
        float yx[4], yh[4];
#pragma unroll
        for (int i = 0; i < 4; i++) {
            int n = m0 + lr0 + i;
            yx[i] = g_YX[(((size_t)z * Tq + t) * Nq + n) * Fq + l];
            yh[i] = ys[(lr0 + i) * 34 + l];
        }
        float gacc[4][4][4];
#pragma unroll
        for (int i = 0; i < 4; i++)
#pragma unroll
            for (int p = 0; p < 4; p++)
#pragma unroll
                for (int q = 0; q < 4; q++) gacc[i][p][q] = 0.0f;
#pragma unroll
        for (int k = 0; k < 32; k++) {
            float ykx[4], ykh[4];
#pragma unroll
            for (int i = 0; i < 4; i++) {
                ykx[i] = __shfl_sync(0xffffffffu, yx[i], k);
                ykh[i] = __shfl_sync(0xffffffffu, yh[i], k);
            }
#pragma unroll
            for (int p = 0; p < 4; p++) {
                float4 wv = Wp[k * 128 + p * 32 + l];
#pragma unroll
                for (int i = 0; i < 4; i++) {
                    gacc[i][p][0] = fmaf(ykx[i], wv.x, gacc[i][p][0]);
                    gacc[i][p][1] = fmaf(ykx[i], wv.y, gacc[i][p][1]);
                    gacc[i][p][2] = fmaf(ykh[i], wv.z, gacc[i][p][2]);
                    gacc[i][p][3] = fmaf(ykh[i], wv.w, gacc[i][p][3]);
                }
            }
        }
#pragma unroll
        for (int i = 0; i < 4; i++) {
            int n = m0 + lr0 + i;
            float s[4];
#pragma unroll
            for (int p = 0; p < 4; p++) {
                float4 bb = bp[p * 32 + l];
                float gx = (gacc[i][p][0] + bb.x) * sigf(gacc[i][p][1] + bb.y);
                float gh = (gacc[i][p][2] + bb.z) * sigf(gacc[i][p][3] + bb.w);
                s[p] = gx + gh;
            }
            float f  = sigf(s[0]);
            float ig = sigf(s[1]);
            float o  = sigf(s[3]);
            size_t ci = ((size_t)z * Nq + n) * Fq + l;
            float cn = f * g_c[ci] + ig * tanhf(s[2]);
            g_c[ci] = cn;
            float hm = o * tanhf(cn);
            g_ht[((size_t)z * Fq + l) * Nq + n] = __float2half(hm);
            if (t == Tq - 1) last_c[ci] = cn;
        }
    }
}

// ---------------------------------------------------------------------------
// step2: Y2 = adj @ h_mid^T (BN=32, full K) FUSED with gates2.
// y2 stays in smem; ym read from g_Y1m. Outputs h/m state (fp16 transposed),
// hidden, last_h/last_m.
// ---------------------------------------------------------------------------
__global__ __launch_bounds__(256, 2) void step2_kernel(const float* __restrict__ W8,
                                                       const float* __restrict__ bias8,
                                                       int t, float* __restrict__ hidden,
                                                       float* __restrict__ last_h,
                                                       float* __restrict__ last_m) {
    extern __shared__ char smc[];
    const int z = blockIdx.z;
    const int m0 = blockIdx.x * 128;
    const __half* gA = g_Ah + (size_t)z * Nq * Nq + (size_t)m0 * Nq;
    const __half* gB = g_ht + (size_t)z * 32 * Nq;
    GEMM_MAINLOOP(32, 64, gA, gB)

    float* ys  = (float*)smc;                         // [128][34] fp32 (17408 B)
    float4* Wp = (float4*)(smc + 17408);              // 3072 float4 (49152 B)
    float4* bp = (float4*)(smc + 17408 + 49152);      // 96 float4 (1536 B)
    __syncthreads();

    {
#pragma unroll
        for (int mf = 0; mf < 2; mf++)
#pragma unroll
            for (int nf = 0; nf < NF; nf++) {
                int lr = wm * 32 + mf * 16 + (lane >> 2);
                int c = wn * WN + nf * 8 + (lane & 3) * 2;
                *(float2*)&ys[lr * 34 + c] = make_float2(acc[mf][nf][0], acc[mf][nf][1]);
                *(float2*)&ys[(lr + 8) * 34 + c] = make_float2(acc[mf][nf][2], acc[mf][nf][3]);
            }
    }
    for (int idx = tid; idx < 3072; idx += 256) {
        int k = idx / 96, r = idx % 96, p = r >> 5, l2 = r & 31;
        const float* W0 = W8 + (2 * p) * (Fq * 2 * Fq) + k * (2 * Fq);
        const float* W1 = W8 + (2 * p + 1) * (Fq * 2 * Fq) + k * (2 * Fq);
        Wp[idx] = make_float4(W0[l2], W0[l2 + 32], W1[l2], W1[l2 + 32]);
    }
    if (tid < 96) {
        int p = tid >> 5, l2 = tid & 31;
        bp[tid] = make_float4(bias8[(2 * p) * 64 + l2], bias8[(2 * p) * 64 + 32 + l2],
                              bias8[(2 * p + 1) * 64 + l2], bias8[(2 * p + 1) * 64 + 32 + l2]);
    }
    __syncthreads();

    const int l = lane;
#pragma unroll 1
    for (int blk = 0; blk < 4; blk++) {
        int lr0 = wid * 16 + blk * 4;
        float y2[4], ym[4];
#pragma unroll
        for (int i = 0; i < 4; i++) {
            int n = m0 + lr0 + i;
            y2[i] = ys[(lr0 + i) * 34 + l];
            ym[i] = g_Y1m[((size_t)z * Nq + n) * Fq + l];
        }
        float gacc[4][3][4];
#pragma unroll
        for (int i = 0; i < 4; i++)
#pragma unroll
            for (int p = 0; p < 3; p++)
#pragma unroll
                for (int q = 0; q < 4; q++) gacc[i][p][q] = 0.0f;
#pragma unroll
        for (int k = 0; k < 32; k++) {
            float yk2[4], ykm[4];
#pragma unroll
            for (int i = 0; i < 4; i++) {
                yk2[i] = __shfl_sync(0xffffffffu, y2[i], k);
                ykm[i] = __shfl_sync(0xffffffffu, ym[i], k);
            }
#pragma unroll
            for (int p = 0; p < 3; p++) {
                float4 wv = Wp[k * 96 + p * 32 + l];
#pragma unroll
                for (int i = 0; i < 4; i++) {
                    gacc[i][p][0] = fmaf(yk2[i], wv.x, gacc[i][p][0]);
                    gacc[i][p][1] = fmaf(yk2[i], wv.y, gacc[i][p][1]);
                    gacc[i][p][2] = fmaf(ykm[i], wv.z, gacc[i][p][2]);
                    gacc[i][p][3] = fmaf(ykm[i], wv.w, gacc[i][p][3]);
                }
            }
        }
#pragma unroll
        for (int i = 0; i < 4; i++) {
            int n = m0 + lr0 + i;
            float s[3];
#pragma unroll
            for (int p = 0; p < 3; p++) {
                float4 bb = bp[p * 32 + l];
                float gx = (gacc[i][p][0] + bb.x) * sigf(gacc[i][p][1] + bb.y);
                float gh = (gacc[i][p][2] + bb.z) * sigf(gacc[i][p][3] + bb.w);
                s[p] = gx + gh;
            }
            float i2 = sigf(s[0]);
            float gg = sigf(s[1]);
            float o2 = sigf(s[2]);
            size_t ci = ((size_t)z * Nq + n) * Fq + l;
            float mo = g_m[ci];
            float mn = i2 * mo + (1.0f - i2) * gg;
            float hn = mn * o2;
            g_m[ci] = mn;
            g_St[((size_t)z * 64 + l) * Nq + n]      = __float2half(hn);
            g_St[((size_t)z * 64 + 32 + l) * Nq + n] = __float2half(mn);
            hidden[(((size_t)z * Tq + t) * Nq + n) * Fq + l] = hn;
            if (t == Tq - 1) {
                last_h[ci] = hn;
                last_m[ci] = mn;
            }
        }
    }
}

// ---------------------------------------------------------------------------
// kernel_launch — 2 fused kernels per step; precompute piece 0 on the main
// stream (fills the pre-chain bubble), pieces 1..5 on the side stream.
// ---------------------------------------------------------------------------
extern "C" void kernel_launch(void* const* d_in, const int* in_sizes, int n_in,
                              void* d_out, int out_size) {
    (void)in_sizes; (void)n_in; (void)out_size;
    const float* x    = (const float*)d_in[0];
    const float* adj  = (const float*)d_in[1];
    const float* W    = (const float*)d_in[2];
    const float* bias = (const float*)d_in[3];

    float* hidden = (float*)d_out;
    float* last_h = hidden + (size_t)Bq * Tq * Nq * Fq;
    float* last_c = last_h + (size_t)Bq * Nq * Fq;
    float* last_m = last_c + (size_t)Bq * Nq * Fq;

    float* pYX;
    __half* pxt;
    cudaGetSymbolAddress((void**)&pYX, g_YX);
    cudaGetSymbolAddress((void**)&pxt, g_xt);

    const int PRE_SMEM   = 3 * 2 * (128 * 80 + 64 * 80);          // 92160
    const int S1_SMEM    = 92160;                                 // >= max(GEMM, 85KB epi)
    const int S2_SMEM    = 76800;                                 // >= max(GEMM, 68KB epi)

    static bool inited = false;
    static cudaStream_t s2;
    static cudaEvent_t evFork, evPre[6];
    if (!inited) {
        cudaFuncSetAttribute(pre_gemm,     cudaFuncAttributeMaxDynamicSharedMemorySize, PRE_SMEM);
        cudaFuncSetAttribute(step1_kernel, cudaFuncAttributeMaxDynamicSharedMemorySize, S1_SMEM);
        cudaFuncSetAttribute(step2_kernel, cudaFuncAttributeMaxDynamicSharedMemorySize, S2_SMEM);
        cudaStreamCreateWithFlags(&s2, cudaStreamNonBlocking);
        cudaEventCreateWithFlags(&evFork, cudaEventDisableTiming);
        for (int p = 0; p < 6; p++)
            cudaEventCreateWithFlags(&evPre[p], cudaEventDisableTiming);
        inited = true;
    }

    cudaStream_t s0 = 0;

    convert_adj<<<(Bq * Nq * Nq / 4) / 256, 256, 0, s0>>>(adj);
    init_state<<<(Bq * 2 * Fq * Nq + 255) / 256, 256, 0, s0>>>();
    trans_x<<<dim3(Nq / 64, 1, Bq * Tq), 256, 0, s0>>>(x, pxt);

    cudaEventRecord(evFork, s0);
    // piece 0 (t=0,1) on main stream: fills the bubble before step1(0)
    pre_gemm<<<dim3(Nq / 128, 1, Bq), 256, PRE_SMEM, s0>>>(pxt, pYX);
    // pieces 1..5 on side stream
    cudaStreamWaitEvent(s2, evFork, 0);
    for (int p = 1; p < 6; p++) {
        pre_gemm<<<dim3(Nq / 128, 1, Bq), 256, PRE_SMEM, s2>>>(
            pxt + (size_t)p * 64 * Nq, pYX + (size_t)p * 2 * Nq * Fq);
        cudaEventRecord(evPre[p], s2);
    }

    for (int t = 0; t < Tq; t++) {
        if ((t & 1) == 0 && t >= 2) cudaStreamWaitEvent(s0, evPre[t >> 1], 0);
        step1_kernel<<<dim3(Nq / 128, 1, Bq), 256, S1_SMEM, s0>>>(W, bias, t, last_c);
        step2_kernel<<<dim3(Nq / 128, 1, Bq), 256, S2_SMEM, s0>>>(
            W + 8 * (Fq * 2 * Fq), bias + 8 * (2 * Fq), t, hidden, last_h, last_m);
    }
}

// round 15
// speedup vs baseline: 1.1339x; 1.1339x over previous
#include <cuda_runtime.h>
#include <cuda_fp16.h>
#include <cstdint>

#define Bq 4
#define Tq 12
#define Nq 4096
#define Fq 32
#define NCTA 256

// ---------------------------------------------------------------------------
// PTX helpers — Ampere-era only (compute_103-safe; tcgen05 rejected at the
// compute_103 virtual arch; s8 IMMA slow (R5); launch-per-phase chain costs
// ~80us/step in gaps (R12/R14 accounting) -> persistent kernel).
// ---------------------------------------------------------------------------
__device__ __forceinline__ uint32_t smem_to_u32(const void* p) {
    uint32_t a;
    asm("{ .reg .u64 t; cvta.to.shared.u64 t, %1; cvt.u32.u64 %0, t; }" : "=r"(a) : "l"(p));
    return a;
}

#define CP_ASYNC16(dst, src) \
    asm volatile("cp.async.cg.shared.global [%0], [%1], 16;" :: "r"(dst), "l"(src) : "memory")
#define CP_COMMIT() asm volatile("cp.async.commit_group;" ::: "memory")
#define CP_WAIT0()  asm volatile("cp.async.wait_group 0;" ::: "memory")
#define CP_WAIT1()  asm volatile("cp.async.wait_group 1;" ::: "memory")

__device__ __forceinline__ void ldsm4(uint32_t addr, uint32_t* r) {
    asm volatile("ldmatrix.sync.aligned.m8n8.x4.shared.b16 {%0,%1,%2,%3}, [%4];"
                 : "=r"(r[0]), "=r"(r[1]), "=r"(r[2]), "=r"(r[3]) : "r"(addr));
}
__device__ __forceinline__ void mma_f16(float* d, const uint32_t* a, uint32_t b0, uint32_t b1) {
    asm volatile("mma.sync.aligned.m16n8k16.row.col.f32.f16.f16.f32 "
                 "{%0,%1,%2,%3},{%4,%5,%6,%7},{%8,%9},{%0,%1,%2,%3};"
                 : "+f"(d[0]), "+f"(d[1]), "+f"(d[2]), "+f"(d[3])
                 : "r"(a[0]), "r"(a[1]), "r"(a[2]), "r"(a[3]), "r"(b0), "r"(b1));
}

// ---------------------------------------------------------------------------
// Device scratch
// ---------------------------------------------------------------------------
__device__ __align__(128) __half g_Ah[(size_t)Bq * Nq * Nq];
__device__ __align__(128) __half g_xt[(size_t)Bq * Tq * Fq * Nq];   // [b][t*32+f][n]
__device__ __align__(128) __half g_St[(size_t)Bq * 2 * Fq * Nq];    // [b][64][n]  (h|m)
__device__ __align__(128) __half g_ht[(size_t)Bq * Fq * Nq];        // [b][32][n]  (h_mid)

__device__ __align__(128) float g_YX[(size_t)Bq * Tq * Nq * Fq];
__device__ __align__(128) float g_Y1[2 * (size_t)Bq * Nq * 2 * Fq]; // split-K=2 partials
__device__ __align__(128) float g_Y2[2 * (size_t)Bq * Nq * Fq];
__device__ __align__(128) float g_m [(size_t)Bq * Nq * Fq];
__device__ __align__(128) float g_c [(size_t)Bq * Nq * Fq];

__device__ unsigned g_bar;

__device__ __forceinline__ float sigf(float x) { return 1.0f / (1.0f + __expf(-x)); }

// ---------------------------------------------------------------------------
// grid barrier: release (all-thread fence) -> arrive -> spin -> rejoin.
// Cross-phase global reads are L1-safe by construction (cp.async.cg / __ldcg /
// same-CTA addresses / once-per-launch addresses), so no post-IVALL needed.
// ---------------------------------------------------------------------------
__device__ __forceinline__ void grid_bar(unsigned target) {
    __threadfence();
    __syncthreads();
    if (threadIdx.x == 0) {
        atomicAdd(&g_bar, 1u);
        while (*(volatile unsigned*)&g_bar < target) __nanosleep(64);
    }
    __syncthreads();
}

// ---------------------------------------------------------------------------
// adj -> fp16
// ---------------------------------------------------------------------------
__global__ __launch_bounds__(256) void convert_adj(const float* __restrict__ adj) {
    size_t i = (size_t)blockIdx.x * 256 + threadIdx.x;
    float4 v = ((const float4*)adj)[i];
    __half2 p0 = __floats2half2_rn(v.x, v.y);
    __half2 p1 = __floats2half2_rn(v.z, v.w);
    uint2 w;
    w.x = *(uint32_t*)&p0; w.y = *(uint32_t*)&p1;
    ((uint2*)g_Ah)[i] = w;
}

__global__ void init_state() {
    int i = blockIdx.x * blockDim.x + threadIdx.x;
    if (i == 0) g_bar = 0;
    if (i < Bq * Nq * Fq) { g_m[i] = 1.0f; g_c[i] = 1.0f; }
    if (i < Bq * 2 * Fq * Nq) g_St[i] = __float2half(1.0f);
}

// ---------------------------------------------------------------------------
// transpose x: [z][4096][32] fp32 -> [z][32][4096] fp16
// ---------------------------------------------------------------------------
__global__ __launch_bounds__(256) void trans_x(const float* __restrict__ V,
                                               __half* __restrict__ T) {
    __shared__ float tile[64][33];
    const int z = blockIdx.z;
    const int n0 = blockIdx.x * 64;
    const float* v = V + (size_t)z * Nq * 32 + (size_t)n0 * 32;
    const int tid = threadIdx.x;
#pragma unroll
    for (int idx = tid; idx < 64 * 32; idx += 256)
        tile[idx >> 5][idx & 31] = v[idx];
    __syncthreads();
    __half* t = T + (size_t)z * 32 * Nq;
#pragma unroll
    for (int idx = tid; idx < 64 * 32; idx += 256) {
        int f = idx >> 6, j = idx & 63;
        t[(size_t)f * Nq + n0 + j] = __float2half(tile[j][f]);
    }
}

// ---------------------------------------------------------------------------
// GEMM phase (device function): BM=128, superchunk K=64, 3 superbuffers,
// one barrier per superchunk (R12-proven). Output col j of row r:
//   yb[r*rstride + (j>>5)*gstride + (j&31)]
// ---------------------------------------------------------------------------
template <int BN>
__device__ void gemm_phase(char* smc, const __half* __restrict__ gA,
                           const __half* __restrict__ gB, float* __restrict__ yb,
                           int rstride, int gstride, int m0, int nss) {
    constexpr int RB = 80;
    constexpr int A_BYTES = 128 * RB;
    constexpr int B_BYTES = BN * RB;
    constexpr int OFF_B = A_BYTES;
    constexpr int SUB = A_BYTES + B_BYTES;
    constexpr int STAGE = 2 * SUB;
    constexpr int WN = BN / 2;
    constexpr int NF = WN / 8;
    constexpr int NB = (NF + 1) / 2;

    const uint32_t sbase = smem_to_u32(smc);
    const int tid = threadIdx.x;
    const int wid = tid >> 5, lane = tid & 31;
    const int wm = wid & 3, wn = wid >> 2;
    const int arow = tid >> 2;
    const int acol = tid & 3;
    const int brow = (BN == 64) ? (tid >> 2) : ((tid & 127) >> 2);
    const bool bact = (BN == 64) || (tid < 128);

    float acc[2][NF][4];
#pragma unroll
    for (int mf = 0; mf < 2; mf++)
#pragma unroll
        for (int nf = 0; nf < NF; nf++)
#pragma unroll
            for (int q = 0; q < 4; q++) acc[mf][nf][q] = 0.0f;

    auto issue = [&](int s) {
        const uint32_t st = sbase + (uint32_t)(s % 3) * STAGE;
#pragma unroll
        for (int kc = 0; kc < 2; kc++) {
            const uint32_t sb = st + kc * SUB;
            const int k0 = s * 64 + kc * 32;
#pragma unroll
            for (int rep = 0; rep < 2; rep++) {
                int r = rep * 64 + arow;
                CP_ASYNC16(sb + r * RB + acol * 16, gA + (size_t)r * Nq + k0 + acol * 8);
            }
            if (bact)
                CP_ASYNC16(sb + OFF_B + brow * RB + acol * 16,
                           gB + (size_t)brow * Nq + k0 + acol * 8);
        }
    };

    issue(0); CP_COMMIT();
    issue(1); CP_COMMIT();

    const int a_r = (lane & 15);
    const int a_k = (lane >> 4) * 16;
    const int b_r = ((lane >> 4) << 3) + (lane & 7);
    const int b_k = ((lane >> 3) & 1) * 16;

#pragma unroll 1
    for (int s = 0; s < nss; s++) {
        if (s + 1 < nss) { CP_WAIT1(); } else { CP_WAIT0(); }
        __syncthreads();
        if (s + 2 < nss) { issue(s + 2); CP_COMMIT(); }

        const uint32_t st = sbase + (uint32_t)(s % 3) * STAGE;
#pragma unroll
        for (int kc = 0; kc < 2; kc++) {
            const uint32_t sb = st + kc * SUB;
#pragma unroll
            for (int ks = 0; ks < 2; ks++) {
                uint32_t ah[2][4];
#pragma unroll
                for (int mf = 0; mf < 2; mf++)
                    ldsm4(sb + (wm * 32 + mf * 16 + a_r) * RB + ks * 32 + a_k, ah[mf]);
                uint32_t bh[NB][4];
#pragma unroll
                for (int nb = 0; nb < NB; nb++)
                    ldsm4(sb + OFF_B + (wn * WN + nb * 16 + b_r) * RB + ks * 32 + b_k, bh[nb]);
#pragma unroll
                for (int mf = 0; mf < 2; mf++)
#pragma unroll
                    for (int nf = 0; nf < NF; nf++) {
                        const int nb = nf >> 1, pr = (nf & 1) * 2;
                        mma_f16(acc[mf][nf], ah[mf], bh[nb][pr], bh[nb][pr + 1]);
                    }
            }
        }
    }

#pragma unroll
    for (int mf = 0; mf < 2; mf++)
#pragma unroll
        for (int nf = 0; nf < NF; nf++) {
            int r = m0 + wm * 32 + mf * 16 + (lane >> 2);
            int cj = wn * WN + nf * 8 + (lane & 3) * 2;
            size_t off = (size_t)(cj >> 5) * gstride + (cj & 31);
            float* o0 = yb + (size_t)r * rstride + off;
            float* o1 = yb + (size_t)(r + 8) * rstride + off;
            *(float2*)o0 = make_float2(acc[mf][nf][0], acc[mf][nf][1]);
            *(float2*)o1 = make_float2(acc[mf][nf][2], acc[mf][nf][3]);
        }
}

// ---------------------------------------------------------------------------
// gates1 phase: LSTM gates 0..7, row-blocked (R10/R12-proven), 2 partials
// read via __ldcg (L1-bypass: same addresses recur every t).
// ---------------------------------------------------------------------------
__device__ void gates1_phase(char* smc, const float* __restrict__ W,
                             const float* __restrict__ bias, int t,
                             float* __restrict__ last_c) {
    float4* Wp = (float4*)smc;                 // 4096 float4 = 65536 B
    float4* bp = (float4*)(smc + 65536);       // 128 float4
    const long long PS1 = (long long)Bq * Nq * 64;
    const int tid = threadIdx.x;

    for (int idx = tid; idx < 4096; idx += 256) {
        int l = idx & 31, p = (idx >> 5) & 3, k = idx >> 7;
        const float* W0 = W + (2 * p) * (Fq * 2 * Fq) + k * (2 * Fq);
        const float* W1 = W + (2 * p + 1) * (Fq * 2 * Fq) + k * (2 * Fq);
        Wp[idx] = make_float4(W0[l], W0[l + 32], W1[l], W1[l + 32]);
    }
    if (tid < 128) {
        int l = tid & 31, p = tid >> 5;
        bp[p * 32 + l] = make_float4(bias[(2 * p) * 64 + l], bias[(2 * p) * 64 + 32 + l],
                                     bias[(2 * p + 1) * 64 + l], bias[(2 * p + 1) * 64 + 32 + l]);
    }
    __syncthreads();

    const int w = tid >> 5, l = tid & 31;
#pragma unroll 1
    for (int r0 = blockIdx.x * 32 + w * 4; r0 < Bq * Nq; r0 += NCTA * 32) {
        float yx[4], yh[4];
#pragma unroll
        for (int i = 0; i < 4; i++) {
            int row = r0 + i;
            int b = row >> 12, n = row & (Nq - 1);
            yx[i] = g_YX[(((size_t)b * Tq + t) * Nq + n) * Fq + l];
            yh[i] = __ldcg(&g_Y1[(size_t)row * 64 + l]) +
                    __ldcg(&g_Y1[PS1 + (size_t)row * 64 + l]);
        }

        float acc[4][4][4];
#pragma unroll
        for (int i = 0; i < 4; i++)
#pragma unroll
            for (int p = 0; p < 4; p++)
#pragma unroll
                for (int q = 0; q < 4; q++) acc[i][p][q] = 0.0f;

#pragma unroll
        for (int k = 0; k < 32; k++) {
            float ykx[4], ykh[4];
#pragma unroll
            for (int i = 0; i < 4; i++) {
                ykx[i] = __shfl_sync(0xffffffffu, yx[i], k);
                ykh[i] = __shfl_sync(0xffffffffu, yh[i], k);
            }
#pragma unroll
            for (int p = 0; p < 4; p++) {
                float4 wv = Wp[k * 128 + p * 32 + l];
#pragma unroll
                for (int i = 0; i < 4; i++) {
                    acc[i][p][0] = fmaf(ykx[i], wv.x, acc[i][p][0]);
                    acc[i][p][1] = fmaf(ykx[i], wv.y, acc[i][p][1]);
                    acc[i][p][2] = fmaf(ykh[i], wv.z, acc[i][p][2]);
                    acc[i][p][3] = fmaf(ykh[i], wv.w, acc[i][p][3]);
                }
            }
        }

#pragma unroll
        for (int i = 0; i < 4; i++) {
            int row = r0 + i;
            int b = row >> 12, n = row & (Nq - 1);
            float s[4];
#pragma unroll
            for (int p = 0; p < 4; p++) {
                float4 bb = bp[p * 32 + l];
                float gx = (acc[i][p][0] + bb.x) * sigf(acc[i][p][1] + bb.y);
                float gh = (acc[i][p][2] + bb.z) * sigf(acc[i][p][3] + bb.w);
                s[p] = gx + gh;
            }
            float f  = sigf(s[0]);
            float ig = sigf(s[1]);
            float o  = sigf(s[3]);
            size_t ci = (size_t)row * Fq + l;
            float cn = f * g_c[ci] + ig * tanhf(s[2]);
            g_c[ci] = cn;
            float hm = o * tanhf(cn);
            g_ht[((size_t)b * Fq + l) * Nq + n] = __float2half(hm);
            if (t == Tq - 1) last_c[ci] = cn;
        }
    }
}

// ---------------------------------------------------------------------------
// gates2 phase: memory gates 8..13, row-blocked, partials via __ldcg.
// ---------------------------------------------------------------------------
__device__ void gates2_phase(char* smc, const float* __restrict__ W8,
                             const float* __restrict__ bias8, int t,
                             float* __restrict__ hidden,
                             float* __restrict__ last_h,
                             float* __restrict__ last_m) {
    float4* Wp = (float4*)smc;                 // 3072 float4 = 49152 B
    float4* bp = (float4*)(smc + 49152);       // 96 float4
    const long long PS1 = (long long)Bq * Nq * 64;
    const long long PS2 = (long long)Bq * Nq * 32;
    const int tid = threadIdx.x;

    for (int idx = tid; idx < 3072; idx += 256) {
        int k = idx / 96, r = idx % 96, p = r >> 5, l = r & 31;
        const float* W0 = W8 + (2 * p) * (Fq * 2 * Fq) + k * (2 * Fq);
        const float* W1 = W8 + (2 * p + 1) * (Fq * 2 * Fq) + k * (2 * Fq);
        Wp[idx] = make_float4(W0[l], W0[l + 32], W1[l], W1[l + 32]);
    }
    if (tid < 96) {
        int p = tid >> 5, l = tid & 31;
        bp[tid] = make_float4(bias8[(2 * p) * 64 + l], bias8[(2 * p) * 64 + 32 + l],
                              bias8[(2 * p + 1) * 64 + l], bias8[(2 * p + 1) * 64 + 32 + l]);
    }
    __syncthreads();

    const int w = tid >> 5, l = tid & 31;
#pragma unroll 1
    for (int r0 = blockIdx.x * 32 + w * 4; r0 < Bq * Nq; r0 += NCTA * 32) {
        float y2[4], ym[4];
#pragma unroll
        for (int i = 0; i < 4; i++) {
            int row = r0 + i;
            y2[i] = __ldcg(&g_Y2[(size_t)row * 32 + l]) +
                    __ldcg(&g_Y2[PS2 + (size_t)row * 32 + l]);
            ym[i] = __ldcg(&g_Y1[(size_t)row * 64 + 32 + l]) +
                    __ldcg(&g_Y1[PS1 + (size_t)row * 64 + 32 + l]);
        }

        float acc[4][3][4];
#pragma unroll
        for (int i = 0; i < 4; i++)
#pragma unroll
            for (int p = 0; p < 3; p++)
#pragma unroll
                for (int q = 0; q < 4; q++) acc[i][p][q] = 0.0f;

#pragma unroll
        for (int k = 0; k < 32; k++) {
            float yk2[4], ykm[4];
#pragma unroll
            for (int i = 0; i < 4; i++) {
                yk2[i] = __shfl_sync(0xffffffffu, y2[i], k);
                ykm[i] = __shfl_sync(0xffffffffu, ym[i], k);
            }
#pragma unroll
            for (int p = 0; p < 3; p++) {
                float4 wv = Wp[k * 96 + p * 32 + l];
#pragma unroll
                for (int i = 0; i < 4; i++) {
                    acc[i][p][0] = fmaf(yk2[i], wv.x, acc[i][p][0]);
                    acc[i][p][1] = fmaf(yk2[i], wv.y, acc[i][p][1]);
                    acc[i][p][2] = fmaf(ykm[i], wv.z, acc[i][p][2]);
                    acc[i][p][3] = fmaf(ykm[i], wv.w, acc[i][p][3]);
                }
            }
        }

#pragma unroll
        for (int i = 0; i < 4; i++) {
            int row = r0 + i;
            int b = row >> 12, n = row & (Nq - 1);
            float s[3];
#pragma unroll
            for (int p = 0; p < 3; p++) {
                float4 bb = bp[p * 32 + l];
                float gx = (acc[i][p][0] + bb.x) * sigf(acc[i][p][1] + bb.y);
                float gh = (acc[i][p][2] + bb.z) * sigf(acc[i][p][3] + bb.w);
                s[p] = gx + gh;
            }
            float i2 = sigf(s[0]);
            float gg = sigf(s[1]);
            float o2 = sigf(s[2]);
            size_t ci = (size_t)row * Fq + l;
            float mo = g_m[ci];
            float mn = i2 * mo + (1.0f - i2) * gg;
            float hn = mn * o2;
            g_m[ci] = mn;
            g_St[((size_t)b * 64 + l) * Nq + n]      = __float2half(hn);
            g_St[((size_t)b * 64 + 32 + l) * Nq + n] = __float2half(mn);
            hidden[(((size_t)b * Tq + t) * Nq + n) * Fq + l] = hn;
            if (t == Tq - 1) {
                last_h[ci] = hn;
                last_m[ci] = mn;
            }
        }
    }
}

// ---------------------------------------------------------------------------
// Persistent kernel: precompute (3 barrier-free phases) + 12 recurrent steps,
// 4 grid barriers per step. 256 CTAs, 2/SM, all co-resident by construction.
// ---------------------------------------------------------------------------
__global__ __launch_bounds__(256, 2) void persist_kernel(
    const float* __restrict__ W, const float* __restrict__ bias,
    float* __restrict__ hidden, float* __restrict__ last_h,
    float* __restrict__ last_c, float* __restrict__ last_m) {
    extern __shared__ char smc[];
    const int cta = blockIdx.x;
    unsigned lvl = 0;

    // --- precompute adj @ x: 3 phases x (2 slabs x 128 tiles), full-K ---
    {
        const int sl_half = cta >> 7;         // 0..1
        const int tile = cta & 127;
        const int z = tile >> 5, m0 = (tile & 31) * 128;
        const __half* gA = g_Ah + (size_t)z * Nq * Nq + (size_t)m0 * Nq;
#pragma unroll 1
        for (int ph = 0; ph < 3; ph++) {
            const int sl = ph * 2 + sl_half;
            const __half* gB = g_xt + ((size_t)z * Tq * Fq + sl * 64) * Nq;
            float* yb = g_YX + ((size_t)z * Tq + sl * 2) * Nq * Fq;
            gemm_phase<64>(smc, gA, gB, yb, Fq, Nq * Fq, m0, Nq / 64);
        }
    }
    grid_bar(++lvl * NCTA);

    // --- recurrent chain: split-K=2 GEMM phases + gates phases ---
    const int tile = cta >> 1, kh = cta & 1;
    const int z = tile >> 5, m0 = (tile & 31) * 128;
    const __half* gA = g_Ah + (size_t)z * Nq * Nq + (size_t)m0 * Nq + kh * 2048;
    const float* W8 = W + 8 * (Fq * 2 * Fq);
    const float* b8 = bias + 8 * (2 * Fq);

#pragma unroll 1
    for (int t = 0; t < Tq; t++) {
        gemm_phase<64>(smc, gA, g_St + (size_t)z * 64 * Nq + kh * 2048,
                       g_Y1 + ((size_t)kh * Bq + z) * Nq * 64, 64, 32, m0, 32);
        grid_bar(++lvl * NCTA);
        gates1_phase(smc, W, bias, t, last_c);
        grid_bar(++lvl * NCTA);
        gemm_phase<32>(smc, gA, g_ht + (size_t)z * 32 * Nq + kh * 2048,
                       g_Y2 + ((size_t)kh * Bq + z) * Nq * 32, 32, 32, m0, 32);
        grid_bar(++lvl * NCTA);
        gates2_phase(smc, W8, b8, t, hidden, last_h, last_m);
        grid_bar(++lvl * NCTA);
    }
}

// ---------------------------------------------------------------------------
// kernel_launch — 4 launches total, single stream.
// ---------------------------------------------------------------------------
extern "C" void kernel_launch(void* const* d_in, const int* in_sizes, int n_in,
                              void* d_out, int out_size) {
    (void)in_sizes; (void)n_in; (void)out_size;
    const float* x    = (const float*)d_in[0];
    const float* adj  = (const float*)d_in[1];
    const float* W    = (const float*)d_in[2];
    const float* bias = (const float*)d_in[3];

    float* hidden = (float*)d_out;
    float* last_h = hidden + (size_t)Bq * Tq * Nq * Fq;
    float* last_c = last_h + (size_t)Bq * Nq * Fq;
    float* last_m = last_c + (size_t)Bq * Nq * Fq;

    __half* pxt;
    cudaGetSymbolAddress((void**)&pxt, g_xt);

    const int P_SMEM = 3 * 2 * (128 * 80 + 64 * 80);  // 92160

    static bool inited = false;
    if (!inited) {
        cudaFuncSetAttribute(persist_kernel, cudaFuncAttributeMaxDynamicSharedMemorySize, P_SMEM);
        inited = true;
    }

    convert_adj<<<(Bq * Nq * Nq / 4) / 256, 256>>>(adj);
    init_state<<<(Bq * 2 * Fq * Nq + 255) / 256, 256>>>();
    trans_x<<<dim3(Nq / 64, 1, Bq * Tq), 256>>>(x, pxt);
    persist_kernel<<<NCTA, 256, P_SMEM>>>(W, bias, hidden, last_h, last_c, last_m);
}